// round 13
// baseline (speedup 1.0000x reference)
#include <cuda_runtime.h>
#include <cuda_bf16.h>
#include <math_constants.h>
#include <cstdint>

#define BATCH 4096
#define DIM 256
#define NEG_INF (-CUDART_INF_F)

// ---------------- static scratch ----------------
__device__ __nv_bfloat16 g_ab[BATCH * DIM];    // normalized bf16
__device__ __nv_bfloat16 g_p0b[BATCH * DIM];
__device__ __nv_bfloat16 g_p1b[BATCH * DIM];
__device__ float g_posdot[2][BATCH];
__device__ unsigned g_maxbits[2][BATCH];

// ---------------- helpers ----------------
__device__ __forceinline__ unsigned enc_f(float f) {
    unsigned u = __float_as_uint(f);
    return (u & 0x80000000u) ? ~u : (u | 0x80000000u);
}
__device__ __forceinline__ float dec_f(unsigned u) {
    u = (u & 0x80000000u) ? (u & 0x7FFFFFFFu) : ~u;
    return __uint_as_float(u);
}
__device__ __forceinline__ uint32_t smem_u32(const void* p) {
    uint32_t a;
    asm("{ .reg .u64 t; cvta.to.shared.u64 t, %1; cvt.u32.u64 %0, t; }" : "=r"(a) : "l"(p));
    return a;
}
__device__ __forceinline__ void cp_async16(uint32_t dst, const void* src) {
    asm volatile("cp.async.cg.shared.global [%0], [%1], 16;" :: "r"(dst), "l"(src) : "memory");
}
#define CP_COMMIT() asm volatile("cp.async.commit_group;" ::: "memory")
#define CP_WAIT1()  asm volatile("cp.async.wait_group 1;" ::: "memory")

__device__ __forceinline__ void ldsm_x4(uint32_t& r0, uint32_t& r1, uint32_t& r2, uint32_t& r3,
                                        uint32_t addr) {
    asm volatile("ldmatrix.sync.aligned.m8n8.x4.shared.b16 {%0,%1,%2,%3}, [%4];"
                 : "=r"(r0), "=r"(r1), "=r"(r2), "=r"(r3) : "r"(addr));
}
__device__ __forceinline__ void mma16816(float* c, const uint32_t* a, const uint32_t* b) {
    asm volatile(
        "mma.sync.aligned.m16n8k16.row.col.f32.bf16.bf16.f32 "
        "{%0,%1,%2,%3}, {%4,%5,%6,%7}, {%8,%9}, {%0,%1,%2,%3};"
        : "+f"(c[0]), "+f"(c[1]), "+f"(c[2]), "+f"(c[3])
        : "r"(a[0]), "r"(a[1]), "r"(a[2]), "r"(a[3]), "r"(b[0]), "r"(b[1]));
}

// ---------------- kernel 1: fused normalize + positive dots ----------------
__global__ void norm_kernel(const float* __restrict__ anchor,
                            const float* __restrict__ positive) {
    int i = blockIdx.x;
    int tid = threadIdx.x;                       // 0..63
    float4 a  = ((const float4*)(anchor  + (size_t)i * DIM))[tid];
    float4 p0 = ((const float4*)(positive + (size_t)i * 2 * DIM))[tid];
    float4 p1 = ((const float4*)(positive + (size_t)i * 2 * DIM + DIM))[tid];

    float s[5];
    s[0] = a.x * a.x + a.y * a.y + a.z * a.z + a.w * a.w;
    s[1] = p0.x * p0.x + p0.y * p0.y + p0.z * p0.z + p0.w * p0.w;
    s[2] = p1.x * p1.x + p1.y * p1.y + p1.z * p1.z + p1.w * p1.w;
    s[3] = a.x * p0.x + a.y * p0.y + a.z * p0.z + a.w * p0.w;
    s[4] = a.x * p1.x + a.y * p1.y + a.z * p1.z + a.w * p1.w;
#pragma unroll
    for (int k = 0; k < 5; k++)
#pragma unroll
        for (int o = 16; o; o >>= 1) s[k] += __shfl_down_sync(0xffffffffu, s[k], o);
    __shared__ float ws[2][5];
    if ((tid & 31) == 0)
#pragma unroll
        for (int k = 0; k < 5; k++) ws[tid >> 5][k] = s[k];
    __syncthreads();
    float na = ws[0][0] + ws[1][0];
    float n0 = ws[0][1] + ws[1][1];
    float n1 = ws[0][2] + ws[1][2];
    float d0 = ws[0][3] + ws[1][3];
    float d1 = ws[0][4] + ws[1][4];
    float ia = 1.0f / fmaxf(sqrtf(na), 1e-12f);
    float i0 = 1.0f / fmaxf(sqrtf(n0), 1e-12f);
    float i1 = 1.0f / fmaxf(sqrtf(n1), 1e-12f);

    if (tid == 0) {
        g_posdot[0][i] = d0 * ia * i0;
        g_posdot[1][i] = d1 * ia * i1;
        g_maxbits[0][i] = 0u;
        g_maxbits[1][i] = 0u;
    }

    uint2 pk;
    __nv_bfloat162 lo, hi;
    lo = __floats2bfloat162_rn(a.x * ia, a.y * ia);
    hi = __floats2bfloat162_rn(a.z * ia, a.w * ia);
    pk.x = *(uint32_t*)&lo; pk.y = *(uint32_t*)&hi;
    ((uint2*)(g_ab + (size_t)i * DIM))[tid] = pk;
    lo = __floats2bfloat162_rn(p0.x * i0, p0.y * i0);
    hi = __floats2bfloat162_rn(p0.z * i0, p0.w * i0);
    pk.x = *(uint32_t*)&lo; pk.y = *(uint32_t*)&hi;
    ((uint2*)(g_p0b + (size_t)i * DIM))[tid] = pk;
    lo = __floats2bfloat162_rn(p1.x * i1, p1.y * i1);
    hi = __floats2bfloat162_rn(p1.z * i1, p1.w * i1);
    pk.x = *(uint32_t*)&lo; pk.y = *(uint32_t*)&hi;
    ((uint2*)(g_p1b + (size_t)i * DIM))[tid] = pk;
}

// ---------------- kernel 2: bf16 mma.sync GEMM + masked max ----------------
// CTA tile 128x256, 8 warps (2m x 4n), warp tile 64x64, K chunks of 64,
// 2-stage cp.async pipeline, kb^(row&7) swizzle, occupancy 1.
// Compact 1-D grid of 1296 blocks:
//   [0,512)     src1 dense (rt 0..31, cp 0..15), [512,1024) src2 dense,
//   [1024,1296) src0 triangle in 256-col tiles: (rtile, cpair) with 2*cpair+1 >= rtile.
//     row-fold over ALL cols (duplicates under max are harmless);
//     col-fold only for cols whose 128-block index > rtile (mirror coverage).
#define TILE_M 128
#define TILE_N 256
#define A_CHUNK (128 * 128)            // 16384 B per stage
#define B_CHUNK (256 * 128)            // 32768 B per stage
#define STAGE_BYTES (A_CHUNK + B_CHUNK)
#define SM_LABC 0                      // 1024 B (256 cols)
#define SM_LABR 1024                   // 512 B
#define SM_MAXR 1536                   // 512 B
#define SM_MAXC 2048                   // 1024 B
#define SM_BUF  3072
#define SM_TOTAL (SM_BUF + 2 * STAGE_BYTES)   // 101376

__global__ __launch_bounds__(256, 1) void gemm_max_kernel(const int* __restrict__ labels) {
    int bid = blockIdx.x;
    int src, rtile, cpair;
    if (bid < 1024) {
        src = 1 + (bid >> 9);
        int t = bid & 511;
        rtile = t >> 4;
        cpair = t & 15;
    } else {
        src = 0;
        int t = bid - 1024;                 // 0..271
        int k = 0, base = 0;
        while (base + 2 * (16 - k) <= t) { base += 2 * (16 - k); k++; }
        int off = t - base;
        int n = 16 - k;
        rtile = 2 * k + (off >= n);
        cpair = k + (off >= n ? off - n : off);
    }

    extern __shared__ char smem[];
    uint32_t smem_base = smem_u32(smem);
    int tid = threadIdx.x;
    int wid = tid >> 5, lane = tid & 31;
    int wm = wid >> 2;                 // 0..1   rows wm*64..
    int wn = wid & 3;                  // 0..3   cols wn*64..

    int colbase = cpair * TILE_N;
    int row0 = rtile * TILE_M;
    const __nv_bfloat16* Bmat = (src == 0) ? g_ab : (src == 1 ? g_p0b : g_p1b);

    // colfold enable (src0 only): col-half h (0/1) enabled iff 2*cpair+h > rtile
    bool cf_any = (src == 0) && (2 * cpair + 1 > rtile);

    if (tid < TILE_N) *(int*)(smem + SM_LABC + tid * 4) = labels[colbase + tid];
    if (tid < TILE_M) {
        *(int*)(smem + SM_LABR + tid * 4) = labels[row0 + tid];
        *(unsigned*)(smem + SM_MAXR + tid * 4) = 0u;
    }
    if (tid < TILE_N) *(unsigned*)(smem + SM_MAXC + tid * 4) = 0u;

    const char* gA = (const char*)(g_ab + (size_t)row0 * DIM);
    const char* gB = (const char*)(Bmat + (size_t)colbase * DIM);

    auto load_stage = [&](int s, int kc) {
        uint32_t abase = smem_base + SM_BUF + s * STAGE_BYTES;
        uint32_t bbase = abase + A_CHUNK;
#pragma unroll
        for (int i = 0; i < 4; i++) {       // A: 128 rows x 8 kb
            int id = tid + i * 256;
            int row = id >> 3, kb = id & 7;
            uint32_t off = row * 128 + ((kb ^ (row & 7)) << 4);
            cp_async16(abase + off, gA + row * 512 + kc * 128 + kb * 16);
        }
#pragma unroll
        for (int i = 0; i < 8; i++) {       // B: 256 rows x 8 kb
            int id = tid + i * 256;
            int row = id >> 3, kb = id & 7;
            uint32_t off = row * 128 + ((kb ^ (row & 7)) << 4);
            cp_async16(bbase + off, gB + row * 512 + kc * 128 + kb * 16);
        }
    };

    float acc[4][8][4];
#pragma unroll
    for (int i = 0; i < 4; i++)
#pragma unroll
        for (int j = 0; j < 8; j++)
#pragma unroll
            for (int k = 0; k < 4; k++) acc[i][j][k] = 0.f;

    int arow_lo = wm * 64 + (lane & 15);
    int brow_lo = wn * 64 + (lane & 7) + ((lane >> 4) << 3);
    int a_kb_lo = lane >> 4;
    int b_kb_lo = (lane >> 3) & 1;

    load_stage(0, 0);
    CP_COMMIT();

#pragma unroll
    for (int kc = 0; kc < 4; kc++) {
        if (kc < 3) load_stage((kc + 1) & 1, kc + 1);
        CP_COMMIT();
        CP_WAIT1();
        __syncthreads();

        uint32_t abase = smem_base + SM_BUF + (kc & 1) * STAGE_BYTES;
        uint32_t bbase = abase + A_CHUNK;
#pragma unroll
        for (int ks = 0; ks < 4; ks++) {
            uint32_t a[4][4];
            int akb = 2 * ks + a_kb_lo;
#pragma unroll
            for (int mf = 0; mf < 4; mf++) {
                int row = arow_lo + mf * 16;
                uint32_t addr = abase + row * 128 + ((akb ^ (row & 7)) << 4);
                ldsm_x4(a[mf][0], a[mf][1], a[mf][2], a[mf][3], addr);
            }
            uint32_t b[8][2];
            int bkb = 2 * ks + b_kb_lo;
#pragma unroll
            for (int nf2 = 0; nf2 < 4; nf2++) {
                int row = brow_lo + nf2 * 16;
                uint32_t addr = bbase + row * 128 + ((bkb ^ (row & 7)) << 4);
                uint32_t r0, r1, r2, r3;
                ldsm_x4(r0, r1, r2, r3, addr);
                b[nf2 * 2][0] = r0; b[nf2 * 2][1] = r1;
                b[nf2 * 2 + 1][0] = r2; b[nf2 * 2 + 1][1] = r3;
            }
#pragma unroll
            for (int mf = 0; mf < 4; mf++)
#pragma unroll
                for (int nfi = 0; nfi < 8; nfi++)
                    mma16816(acc[mf][nfi], a[mf], b[nfi]);
        }
        __syncthreads();
    }

    // ---- epilogue ----
    int g = lane >> 2, tg = lane & 3;
    const int* labC = (const int*)(smem + SM_LABC);
    const int* labR = (const int*)(smem + SM_LABR);
    unsigned* smaxr = (unsigned*)(smem + SM_MAXR);
    unsigned* smaxc = (unsigned*)(smem + SM_MAXC);

    // row-fold: masked max over this warp's 64 columns, per row (all cols valid)
#pragma unroll
    for (int mf = 0; mf < 4; mf++) {
#pragma unroll
        for (int h = 0; h < 2; h++) {
            int row = wm * 64 + mf * 16 + g + h * 8;
            int rl = labR[row];
            float m = NEG_INF;
#pragma unroll
            for (int nfi = 0; nfi < 8; nfi++) {
                int col = wn * 64 + nfi * 8 + 2 * tg;
                if (labC[col] != rl)     m = fmaxf(m, acc[mf][nfi][h * 2 + 0]);
                if (labC[col + 1] != rl) m = fmaxf(m, acc[mf][nfi][h * 2 + 1]);
            }
            atomicMax(&smaxr[row], enc_f(m));
        }
    }

    // col-fold (mirror of symmetric tiles): per-col masked max over warp's 64 rows
    if (cf_any) {
#pragma unroll
        for (int nfi = 0; nfi < 8; nfi++) {
#pragma unroll
            for (int cpos = 0; cpos < 2; cpos++) {
                int col = wn * 64 + nfi * 8 + 2 * tg + cpos;
                int cl = labC[col];
                float m = NEG_INF;
#pragma unroll
                for (int mf = 0; mf < 4; mf++) {
#pragma unroll
                    for (int h = 0; h < 2; h++) {
                        int row = wm * 64 + mf * 16 + g + h * 8;
                        if (labR[row] != cl) m = fmaxf(m, acc[mf][nfi][h * 2 + cpos]);
                    }
                }
#pragma unroll
                for (int o = 4; o < 32; o <<= 1) m = fmaxf(m, __shfl_xor_sync(0xffffffffu, m, o));
                if (g == 0 && (2 * cpair + (col >> 7)) > rtile)
                    atomicMax(&smaxc[col], enc_f(m));
            }
        }
    }

    __syncthreads();
    if (tid < TILE_M) {
        unsigned e = smaxr[tid];
        int grow = row0 + tid;
        if (src == 0) {
            atomicMax(&g_maxbits[0][grow], e);
            atomicMax(&g_maxbits[1][grow], e);
        } else {
            atomicMax(&g_maxbits[src - 1][grow], e);
        }
    }
    if (src == 0) {
        // tid covers all 256 cols
        int colblock = 2 * cpair + (tid >> 7);
        if (colblock > rtile) {
            unsigned ec = smaxc[tid];
            int gcol = colbase + tid;
            atomicMax(&g_maxbits[0][gcol], ec);
            atomicMax(&g_maxbits[1][gcol], ec);
        }
    }
}

// ---------------- kernel 3: fused loss + reduction (single block) ----------------
__global__ void loss_kernel(float* __restrict__ out) {
    int tid = threadIdx.x;                 // 0..1023
    float s = 0.f;
#pragma unroll
    for (int k = 0; k < 8; k++) {
        int idx = tid + k * 1024;
        int v = idx >> 12;
        int i = idx & (BATCH - 1);
        float pd = g_posdot[v][i];
        float nd = dec_f(g_maxbits[v][i]);
        float pos = sqrtf(fmaxf(2.0f - 2.0f * pd, 1e-12f));
        float neg = sqrtf(fmaxf(2.0f - 2.0f * nd, 1e-12f));
        s += fmaxf(pos - neg + 1.0f, 0.0f);
    }
#pragma unroll
    for (int o = 16; o; o >>= 1) s += __shfl_down_sync(0xffffffffu, s, o);
    __shared__ float ws[32];
    if ((tid & 31) == 0) ws[tid >> 5] = s;
    __syncthreads();
    if (tid < 32) {
        float t = ws[tid];
#pragma unroll
        for (int o = 16; o; o >>= 1) t += __shfl_down_sync(0xffffffffu, t, o);
        if (tid == 0) out[0] = t * (1.0f / 8192.0f);
    }
}

// ---------------------------------------------------------------------------
extern "C" void kernel_launch(void* const* d_in, const int* in_sizes, int n_in,
                              void* d_out, int out_size) {
    const float* anchor = (const float*)d_in[0];
    const float* positive = (const float*)d_in[1];
    const int* labels = (const int*)d_in[2];

    cudaFuncSetAttribute(gemm_max_kernel, cudaFuncAttributeMaxDynamicSharedMemorySize, SM_TOTAL);

    norm_kernel<<<BATCH, 64>>>(anchor, positive);
    gemm_max_kernel<<<1296, 256, SM_TOTAL>>>(labels);
    loss_kernel<<<1, 1024>>>((float*)d_out);
}